// round 7
// baseline (speedup 1.0000x reference)
#include <cuda_runtime.h>
#include <cuda_bf16.h>

typedef unsigned long long u64;

constexpr int B = 4096, T = 200, F = 36;
constexpr int THREADS = 256;
constexpr int BPB  = 32;
constexpr int GRID = B / BPB;     // 128

// shared memory layout (u64 units; h/x stored duplicated {v,v})
constexpr int XBUF_OFF = 0;                       // [2][32][36]
constexpr int H1_OFF   = XBUF_OFF + 2 * 32 * 36;  // [2][32][16]
constexpr int H2_OFF   = H1_OFF + 2 * 32 * 16;    // [2][32][32]
constexpr int H3_OFF   = H2_OFF + 2 * 32 * 32;    // [32][16]
constexpr int XCH_OFF  = H3_OFF + 32 * 16;        // [2 pairs][2 slots][8][32]
constexpr int SMEM_U64 = XCH_OFF + 4 * 8 * 32;
constexpr int SMEM_BYTES = SMEM_U64 * 8;          // 55296

__device__ float g_Wc[6 * 16];
__device__ float g_bc[6];

__device__ __forceinline__ void fma2(u64 &acc, u64 w, u64 x) {
    asm("fma.rn.f32x2 %0, %1, %2, %0;" : "+l"(acc) : "l"(w), "l"(x));
}
__device__ __forceinline__ u64 pk(float v) {
    u64 r; asm("mov.b64 %0, {%1, %1};" : "=l"(r) : "f"(v)); return r;
}
__device__ __forceinline__ u64 pkp(float lo, float hi) {
    u64 r; asm("mov.b64 %0, {%1, %2};" : "=l"(r) : "f"(lo), "f"(hi)); return r;
}
__device__ __forceinline__ void upk(u64 v, float &lo, float &hi) {
    asm("mov.b64 {%0, %1}, %2;" : "=f"(lo), "=f"(hi) : "l"(v));
}
__device__ __forceinline__ float sigf(float x) {
    return __fdividef(1.0f, 1.0f + __expf(-x));
}
__device__ __forceinline__ float tanh_(float x) {
    return __fdividef(2.0f, 1.0f + __expf(-2.0f * x)) - 1.0f;
}
__device__ __forceinline__ float gate_h(u64 ifp, u64 gop, float &c) {
    float pi, pf, pg, po;
    upk(ifp, pi, pf);
    upk(gop, pg, po);
    float cc = fmaf(sigf(pf), c, sigf(pi) * tanh_(pg));
    c = cc;
    return sigf(po) * tanh_(cc);
}
template<int C>
__device__ __forceinline__ void load_wpair(u64* dst, const float* W, int rA, int rB) {
    #pragma unroll
    for (int j4 = 0; j4 < C / 4; j4++) {
        float4 a = __ldg(reinterpret_cast<const float4*>(W + (size_t)rA * C) + j4);
        float4 b = __ldg(reinterpret_cast<const float4*>(W + (size_t)rB * C) + j4);
        dst[j4 * 4 + 0] = pkp(a.x, b.x);
        dst[j4 * 4 + 1] = pkp(a.y, b.y);
        dst[j4 * 4 + 2] = pkp(a.z, b.z);
        dst[j4 * 4 + 3] = pkp(a.w, b.w);
    }
}
// accumulate 8 batches: acc[b] += sum_j wreg[j] * src[b*stride + j]
template<int COLS, int STRIDE>
__device__ __forceinline__ void gemm8(u64 (&acc)[8], const u64* __restrict__ wreg,
                                      const u64* __restrict__ src) {
    #pragma unroll
    for (int j = 0; j < COLS; j += 2) {
        #pragma unroll
        for (int b = 0; b < 8; b++) {
            ulonglong2 v = *reinterpret_cast<const ulonglong2*>(src + b * STRIDE + j);
            fma2(acc[b], wreg[j], v.x);
            fma2(acc[b], wreg[j + 1], v.y);
        }
    }
}

struct XStage { float4 v[5]; };
__device__ __forceinline__ void x_ldg(XStage &s, const float* x, int gb0, int t, int lane) {
    #pragma unroll
    for (int r = 0; r < 5; r++) {
        int f = lane + 32 * r;
        if (f < 144) {
            int b = f / 9, q = f - 9 * b;
            s.v[r] = __ldg(reinterpret_cast<const float4*>(
                x + ((size_t)(gb0 + b) * T + t) * F) + q);
        }
    }
}
__device__ __forceinline__ void x_sts(const XStage &s, u64* XB, int lane) {
    #pragma unroll
    for (int r = 0; r < 5; r++) {
        int f = lane + 32 * r;
        if (f < 144) {
            int b = f / 9, q = f - 9 * b;
            u64* dst = XB + b * 36 + q * 4;
            *reinterpret_cast<ulonglong2*>(dst)     = make_ulonglong2(pk(s.v[r].x), pk(s.v[r].y));
            *reinterpret_cast<ulonglong2*>(dst + 2) = make_ulonglong2(pk(s.v[r].z), pk(s.v[r].w));
        }
    }
}

__global__ void __launch_bounds__(THREADS, 1) lstm_fused(
    const float* __restrict__ x,
    const float* __restrict__ Wih1, const float* __restrict__ Whh1,
    const float* __restrict__ bih1, const float* __restrict__ bhh1,
    const float* __restrict__ Wih2, const float* __restrict__ Whh2,
    const float* __restrict__ bih2, const float* __restrict__ bhh2,
    const float* __restrict__ Wih3, const float* __restrict__ Whh3,
    const float* __restrict__ bih3, const float* __restrict__ bhh3,
    float* __restrict__ out)
{
    extern __shared__ u64 smu[];
    u64* XBUF = smu + XBUF_OFF;
    u64* H1   = smu + H1_OFF;
    u64* H2   = smu + H2_OFF;
    u64* H3   = smu + H3_OFF;
    u64* XCH  = smu + XCH_OFF;

    const int tid  = threadIdx.x;
    const int lane = tid & 31;
    const int wid  = tid >> 5;
    const int blk_b0 = blockIdx.x * BPB;

    for (int idx = tid; idx < 2 * 32 * 16 + 2 * 32 * 32 + 32 * 16; idx += THREADS)
        H1[idx] = 0ull;

    u64 wx[36], wh[32], bias;
    float cst[8];
    #pragma unroll
    for (int b = 0; b < 8; b++) cst[b] = 0.0f;
    XStage xs;

    // ---- weight prologue: registers, loaded once ----
    if (wid < 2) {                       // L1
        int u = lane & 15;
        int rA = (lane < 16) ? u : 32 + u;       // i | g
        int rB = (lane < 16) ? 16 + u : 48 + u;  // f | o
        load_wpair<36>(wx, Wih1, rA, rB);
        load_wpair<16>(wh, Whh1, rA, rB);
        bias = pkp(bih1[rA] + bhh1[rA], bih1[rB] + bhh1[rB]);
        x_ldg(xs, x, blk_b0 + wid * 16, 0, lane);
        x_sts(xs, XBUF + 0 * (32 * 36) + wid * 16 * 36, lane);
    } else if (wid < 6) {                // L2
        int isIF = ((wid - 2) & 1) == 0;
        int u = lane;
        int rA = isIF ? u : 64 + u;
        int rB = isIF ? 32 + u : 96 + u;
        load_wpair<16>(wx, Wih2, rA, rB);
        load_wpair<32>(wh, Whh2, rA, rB);
        bias = pkp(bih2[rA] + bhh2[rA], bih2[rB] + bhh2[rB]);
    } else {                             // L3
        int u = lane & 15;
        int rA = (lane < 16) ? u : 32 + u;
        int rB = (lane < 16) ? 16 + u : 48 + u;
        load_wpair<32>(wx, Wih3, rA, rB);
        load_wpair<16>(wh, Whh3, rA, rB);
        bias = pkp(bih3[rA] + bhh3[rA], bih3[rB] + bhh3[rB]);
    }
    __syncthreads();

    #pragma unroll 1
    for (int i = 0; i <= T + 1; i++) {
        if (wid < 2) {
            // -------- Layer 1: h1(t=i) --------
            if (i < T - 1)
                x_ldg(xs, x, blk_b0 + wid * 16, i + 1, lane);   // prefetch x[i+1]
            if (i < T) {
                const u64* xb = XBUF + (i & 1) * (32 * 36) + wid * 16 * 36;
                const u64* hb = H1 + ((i + 1) & 1) * (32 * 16) + wid * 16 * 16;
                u64 lo[8], hi[8];
                #pragma unroll
                for (int b = 0; b < 8; b++) lo[b] = bias;
                gemm8<36, 36>(lo, wx, xb);
                gemm8<16, 16>(lo, wh, hb);
                #pragma unroll
                for (int b = 0; b < 8; b++) hi[b] = bias;
                gemm8<36, 36>(hi, wx, xb + 8 * 36);
                gemm8<16, 16>(hi, wh, hb + 8 * 16);
                __syncwarp();
                u64* hdst = H1 + (i & 1) * (32 * 16) + wid * 16 * 16;
                int u = lane & 15;
                #pragma unroll
                for (int b = 0; b < 8; b++) {
                    u64 sendv = (lane < 16) ? hi[b] : lo[b];
                    u64 part = __shfl_xor_sync(0xffffffffu, sendv, 16);
                    u64 ifp = (lane < 16) ? lo[b] : part;
                    u64 gop = (lane < 16) ? part : hi[b];
                    int batch = (lane < 16) ? b : b + 8;
                    hdst[batch * 16 + u] = pk(gate_h(ifp, gop, cst[b]));
                }
            }
            if (i < T - 1)
                x_sts(xs, XBUF + ((i + 1) & 1) * (32 * 36) + wid * 16 * 36, lane);
        } else if (wid < 6) {
            // -------- Layer 2: h2(t=i-1) --------
            if (i >= 1 && i <= T) {
                int pair = (wid - 2) >> 1;
                int isIF = ((wid - 2) & 1) == 0;
                const u64* h1s = H1 + ((i + 1) & 1) * (32 * 16) + pair * 16 * 16;
                const u64* h2s = H2 + (i & 1) * (32 * 32) + pair * 16 * 32;
                u64 lo[8], hi[8];
                #pragma unroll
                for (int b = 0; b < 8; b++) lo[b] = bias;
                gemm8<16, 16>(lo, wx, h1s);
                gemm8<32, 32>(lo, wh, h2s);
                #pragma unroll
                for (int b = 0; b < 8; b++) hi[b] = bias;
                gemm8<16, 16>(hi, wx, h1s + 8 * 16);
                gemm8<32, 32>(hi, wh, h2s + 8 * 32);
                // publish half destined for partner; slot0 = IF's, slot1 = GO's
                u64* xm = XCH + (pair * 2 + (isIF ? 0 : 1)) * (8 * 32);
                #pragma unroll
                for (int b = 0; b < 8; b++)
                    xm[b * 32 + lane] = isIF ? hi[b] : lo[b];
                asm volatile("bar.sync %0, %1;" :: "r"(1 + pair), "r"(64) : "memory");
                const u64* xp = XCH + (pair * 2 + (isIF ? 1 : 0)) * (8 * 32);
                u64* hdst = H2 + ((i + 1) & 1) * (32 * 32) + pair * 16 * 32;
                #pragma unroll
                for (int b = 0; b < 8; b++) {
                    u64 pv = xp[b * 32 + lane];
                    u64 ifp = isIF ? lo[b] : pv;
                    u64 gop = isIF ? pv : hi[b];
                    int batch = isIF ? b : b + 8;
                    hdst[batch * 32 + lane] = pk(gate_h(ifp, gop, cst[b]));
                }
            }
        } else {
            // -------- Layer 3: h3(t=i-2) --------
            if (i >= 2) {
                int wb = wid - 6;
                const u64* h2s = H2 + (i & 1) * (32 * 32) + wb * 16 * 32;
                const u64* h3s = H3 + wb * 16 * 16;
                u64 lo[8], hi[8];
                #pragma unroll
                for (int b = 0; b < 8; b++) lo[b] = bias;
                gemm8<32, 32>(lo, wx, h2s);
                gemm8<16, 16>(lo, wh, h3s);
                #pragma unroll
                for (int b = 0; b < 8; b++) hi[b] = bias;
                gemm8<32, 32>(hi, wx, h2s + 8 * 32);
                gemm8<16, 16>(hi, wh, h3s + 8 * 16);
                __syncwarp();
                u64* hdst = H3 + wb * 16 * 16;
                int u = lane & 15;
                #pragma unroll
                for (int b = 0; b < 8; b++) {
                    u64 sendv = (lane < 16) ? hi[b] : lo[b];
                    u64 part = __shfl_xor_sync(0xffffffffu, sendv, 16);
                    u64 ifp = (lane < 16) ? lo[b] : part;
                    u64 gop = (lane < 16) ? part : hi[b];
                    int batch = (lane < 16) ? b : b + 8;
                    hdst[batch * 16 + u] = pk(gate_h(ifp, gop, cst[b]));
                }
            }
        }
        __syncthreads();
    }

    // ---- collapsed head: out = h3_final @ Wc^T + bc ----
    if (tid < 192) {
        int b = tid / 6, cls = tid - b * 6;
        const float* hrow = reinterpret_cast<const float*>(H3 + b * 16);
        float acc0 = g_bc[cls];
        #pragma unroll
        for (int u = 0; u < 16; u++)
            acc0 = fmaf(hrow[2 * u], g_Wc[cls * 16 + u], acc0);
        out[(size_t)(blk_b0 + b) * 6 + cls] = acc0;
    }
}

// Collapse the 3 linear head layers into Wc [6,16], bc [6].
__global__ void head_precompute(
    const float* __restrict__ Wfc1, const float* __restrict__ bfc1,
    const float* __restrict__ Wfc2, const float* __restrict__ bfc2,
    const float* __restrict__ Wcls, const float* __restrict__ bcls)
{
    __shared__ float tmp[6 * 128];
    const int tid = threadIdx.x;

    for (int idx = tid; idx < 6 * 128; idx += blockDim.x) {
        int j = idx / 128, p = idx % 128;
        float s = 0.0f;
        for (int q = 0; q < 32; q++)
            s += Wcls[j * 32 + q] * Wfc2[q * 128 + p];
        tmp[idx] = s;
    }
    __syncthreads();

    for (int idx = tid; idx < 6 * 16; idx += blockDim.x) {
        int j = idx / 16, u = idx % 16;
        float s = 0.0f;
        for (int p = 0; p < 128; p++)
            s += tmp[j * 128 + p] * Wfc1[p * 16 + u];
        g_Wc[idx] = s;
    }
    if (tid < 6) {
        float s = bcls[tid];
        for (int q = 0; q < 32; q++)
            s += Wcls[tid * 32 + q] * bfc2[q];
        for (int p = 0; p < 128; p++)
            s += tmp[tid * 128 + p] * bfc1[p];
        g_bc[tid] = s;
    }
}

extern "C" void kernel_launch(void* const* d_in, const int* in_sizes, int n_in,
                              void* d_out, int out_size)
{
    (void)in_sizes; (void)n_in; (void)out_size;
    const float* x    = (const float*)d_in[0];
    const float* Wih1 = (const float*)d_in[1];
    const float* Whh1 = (const float*)d_in[2];
    const float* bih1 = (const float*)d_in[3];
    const float* bhh1 = (const float*)d_in[4];
    const float* Wih2 = (const float*)d_in[5];
    const float* Whh2 = (const float*)d_in[6];
    const float* bih2 = (const float*)d_in[7];
    const float* bhh2 = (const float*)d_in[8];
    const float* Wih3 = (const float*)d_in[9];
    const float* Whh3 = (const float*)d_in[10];
    const float* bih3 = (const float*)d_in[11];
    const float* bhh3 = (const float*)d_in[12];
    const float* Wfc1 = (const float*)d_in[13];
    const float* bfc1 = (const float*)d_in[14];
    const float* Wfc2 = (const float*)d_in[15];
    const float* bfc2 = (const float*)d_in[16];
    const float* Wcls = (const float*)d_in[17];
    const float* bcls = (const float*)d_in[18];
    float* out = (float*)d_out;

    static bool attr_set = false;
    if (!attr_set) {
        cudaFuncSetAttribute(lstm_fused,
                             cudaFuncAttributeMaxDynamicSharedMemorySize,
                             SMEM_BYTES);
        attr_set = true;
    }

    head_precompute<<<1, 256>>>(Wfc1, bfc1, Wfc2, bfc2, Wcls, bcls);
    lstm_fused<<<GRID, THREADS, SMEM_BYTES>>>(
        x, Wih1, Whh1, bih1, bhh1, Wih2, Whh2, bih2, bhh2,
        Wih3, Whh3, bih3, bhh3, out);
}

// round 8
// speedup vs baseline: 1.3576x; 1.3576x over previous
#include <cuda_runtime.h>
#include <cuda_bf16.h>

typedef unsigned long long u64;

constexpr int B = 4096, T = 200, F = 36;
constexpr int THREADS = 256, WARPS = 8, NBW = 4;   // 4 batches per warp
constexpr int BPB  = WARPS * NBW;                  // 32
constexpr int GRID = B / BPB;                      // 128

// Weight layout (floats). Per lane-block: 4 rows (=2 pairs), element-interleaved
// so one LDS.128 = 2 cols x 2 rows feeds 2 FFMA2. +4 skew per lane block.
constexpr int W1_STRIDE = 212, W2_STRIDE = 196, W3_STRIDE = 196;
constexpr int W1_WHOFF  = 144, W2_WHOFF  = 64,  W3_WHOFF  = 128;
constexpr int OFF_W1 = 0;
constexpr int OFF_W2 = OFF_W1 + 16 * W1_STRIDE;
constexpr int OFF_W3 = OFF_W2 + 32 * W2_STRIDE;
constexpr int OFF_B2 = OFF_W3 + 16 * W3_STRIDE;
constexpr int OFF_B3 = OFF_B2 + 128;
constexpr int OFF_H  = OFF_B3 + 64;

// Per-warp h region (u64 = duplicated f32x2). Padded strides for bank spread.
constexpr int H1_STR = 18, H2_STR = 34, H3_STR = 18;
constexpr int HW_H1 = 0, HW_H2 = 4 * H1_STR, HW_H3 = HW_H2 + 4 * H2_STR;
constexpr int HW_TOTAL = HW_H3 + 4 * H3_STR;
constexpr int SMEM_FLOATS = OFF_H + WARPS * HW_TOTAL * 2;
constexpr int SMEM_BYTES  = SMEM_FLOATS * 4;

__device__ float g_Wc[6 * 16];
__device__ float g_bc[6];
// pre1[b][t][un(16)][pair(2)] u64 = {preA,preB}; pair0={i,f}, pair1={g,o}; biases folded.
__device__ u64 g_pre1[(size_t)B * T * 32];

__device__ __forceinline__ void fma2(u64 &acc, u64 w, u64 x) {
    asm("fma.rn.f32x2 %0, %1, %2, %0;" : "+l"(acc) : "l"(w), "l"(x));
}
__device__ __forceinline__ u64 pk(float v) {
    u64 r; asm("mov.b64 %0, {%1, %1};" : "=l"(r) : "f"(v)); return r;
}
__device__ __forceinline__ u64 pkp(float lo, float hi) {
    u64 r; asm("mov.b64 %0, {%1, %2};" : "=l"(r) : "f"(lo), "f"(hi)); return r;
}
__device__ __forceinline__ void upk(u64 v, float &lo, float &hi) {
    asm("mov.b64 {%0, %1}, %2;" : "=f"(lo), "=f"(hi) : "l"(v));
}
__device__ __forceinline__ float sigf(float x) {
    return __fdividef(1.0f, 1.0f + __expf(-x));
}
__device__ __forceinline__ float tanh_(float x) {
    return __fdividef(2.0f, 1.0f + __expf(-2.0f * x)) - 1.0f;
}

__global__ void __launch_bounds__(THREADS, 1) lstm_fused(
    const float* __restrict__ Whh1,
    const float* __restrict__ Wih2, const float* __restrict__ Whh2,
    const float* __restrict__ bih2, const float* __restrict__ bhh2,
    const float* __restrict__ Wih3, const float* __restrict__ Whh3,
    const float* __restrict__ bih3, const float* __restrict__ bhh3,
    float* __restrict__ out)
{
    extern __shared__ float sm[];
    const int tid = threadIdx.x;

    // ---- stage weights into skewed interleaved layout ----
    // L1 recurrent only (input projection is precomputed into g_pre1)
    for (int idx = tid; idx < 64 * 16; idx += THREADS) {
        int r = idx >> 4, j = idx & 15;
        int q = r >> 4, un = r & 15, p = q >> 1, s = q & 1;
        sm[OFF_W1 + un * W1_STRIDE + W1_WHOFF + p * 32 + 2 * j + s] = Whh1[idx];
    }
    // L2
    for (int idx = tid; idx < 128 * 16; idx += THREADS) {
        int r = idx >> 4, j = idx & 15;
        int q = r >> 5, un = r & 31, p = q >> 1, s = q & 1;
        sm[OFF_W2 + un * W2_STRIDE + p * 32 + 2 * j + s] = Wih2[idx];
    }
    for (int idx = tid; idx < 128 * 32; idx += THREADS) {
        int r = idx >> 5, j = idx & 31;
        int q = r >> 5, un = r & 31, p = q >> 1, s = q & 1;
        sm[OFF_W2 + un * W2_STRIDE + W2_WHOFF + p * 64 + 2 * j + s] = Whh2[idx];
    }
    for (int r = tid; r < 128; r += THREADS) {
        int q = r >> 5, un = r & 31, p = q >> 1, s = q & 1;
        sm[OFF_B2 + (un * 2 + p) * 2 + s] = bih2[r] + bhh2[r];
    }
    // L3
    for (int idx = tid; idx < 64 * 32; idx += THREADS) {
        int r = idx >> 5, j = idx & 31;
        int q = r >> 4, un = r & 15, p = q >> 1, s = q & 1;
        sm[OFF_W3 + un * W3_STRIDE + p * 64 + 2 * j + s] = Wih3[idx];
    }
    for (int idx = tid; idx < 64 * 16; idx += THREADS) {
        int r = idx >> 4, j = idx & 15;
        int q = r >> 4, un = r & 15, p = q >> 1, s = q & 1;
        sm[OFF_W3 + un * W3_STRIDE + W3_WHOFF + p * 32 + 2 * j + s] = Whh3[idx];
    }
    for (int r = tid; r < 64; r += THREADS) {
        int q = r >> 4, un = r & 15, p = q >> 1, s = q & 1;
        sm[OFF_B3 + (un * 2 + p) * 2 + s] = bih3[r] + bhh3[r];
    }
    // zero h region
    for (int i = tid; i < WARPS * HW_TOTAL * 2; i += THREADS)
        sm[OFF_H + i] = 0.0f;
    __syncthreads();

    const int lane = tid & 31;
    const int w    = tid >> 5;
    const int half = lane >> 4;       // 0: batches 0,1   1: batches 2,3 (L1/L3)
    const int hl   = lane & 15;

    u64* hw  = reinterpret_cast<u64*>(sm + OFF_H) + w * HW_TOTAL;
    u64* h1u = hw + HW_H1;
    u64* h2u = hw + HW_H2;
    u64* h3u = hw + HW_H3;

    const float* w1 = sm + OFF_W1 + hl * W1_STRIDE;
    const float* w2 = sm + OFF_W2 + lane * W2_STRIDE;
    const float* w3 = sm + OFF_W3 + hl * W3_STRIDE;
    const u64* b2 = reinterpret_cast<const u64*>(sm + OFF_B2) + lane * 2;
    const u64* b3 = reinterpret_cast<const u64*>(sm + OFF_B3) + hl * 2;

    // L3 recurrent weights -> registers (64 regs), removes 16 LDS.128/step
    u64 wh3r[32];
    #pragma unroll
    for (int p = 0; p < 2; p++)
        #pragma unroll
        for (int j = 0; j < 16; j++)
            wh3r[p * 16 + j] = *reinterpret_cast<const u64*>(w3 + W3_WHOFF + p * 32 + 2 * j);

    const int b0 = blockIdx.x * BPB + w * NBW;
    const int bA = b0 + half * 2 + 0;   // this half-lane's two batches
    const int bB = b0 + half * 2 + 1;

    const ulonglong2* preA = reinterpret_cast<const ulonglong2*>(g_pre1) + (size_t)bA * T * 16 + hl;
    const ulonglong2* preB = reinterpret_cast<const ulonglong2*>(g_pre1) + (size_t)bB * T * 16 + hl;

    const u64* h1self = h1u + half * 2 * H1_STR;
    const u64* h2self = h2u + half * 2 * H2_STR;
    const u64* h3self = h3u + half * 2 * H3_STR;

    float c1[2] = {0.f, 0.f}, c3[2] = {0.f, 0.f};
    float c2[4] = {0.f, 0.f, 0.f, 0.f};

    ulonglong2 pc0 = __ldg(preA);        // pre1 for t=0
    ulonglong2 pc1 = __ldg(preB);

    for (int t = 0; t < T; t++) {
        // prefetch pre1 for t+1 (hidden under this step's compute)
        ulonglong2 pn0, pn1;
        if (t < T - 1) {
            pn0 = __ldg(preA + (size_t)(t + 1) * 16);
            pn1 = __ldg(preB + (size_t)(t + 1) * 16);
        }

        // ================= Layer 1 (H=16, half-warp, 2 local batches) =======
        u64 a1[2][2];
        a1[0][0] = pc0.x; a1[0][1] = pc0.y;     // x-proj + biases precomputed
        a1[1][0] = pc1.x; a1[1][1] = pc1.y;
        #pragma unroll
        for (int j = 0; j < 16; j += 2) {
            ulonglong2 hx0 = *reinterpret_cast<const ulonglong2*>(h1self + 0 * H1_STR + j);
            ulonglong2 hx1 = *reinterpret_cast<const ulonglong2*>(h1self + 1 * H1_STR + j);
            #pragma unroll
            for (int p = 0; p < 2; p++) {
                ulonglong2 wv = *reinterpret_cast<const ulonglong2*>(w1 + W1_WHOFF + p * 32 + 2 * j);
                fma2(a1[0][p], wv.x, hx0.x); fma2(a1[0][p], wv.y, hx0.y);
                fma2(a1[1][p], wv.x, hx1.x); fma2(a1[1][p], wv.y, hx1.y);
            }
        }
        #pragma unroll
        for (int ln = 0; ln < 2; ln++) {
            float gi, gf, gg, go;
            upk(a1[ln][0], gi, gf);
            upk(a1[ln][1], gg, go);
            float cc = fmaf(sigf(gf), c1[ln], sigf(gi) * tanh_(gg));
            c1[ln] = cc;
            h1u[(half * 2 + ln) * H1_STR + hl] = pk(sigf(go) * tanh_(cc));
        }
        __syncwarp();

        // ================= Layer 2 (H=32, full warp, 4 batches) =============
        u64 a2[4][2];
        #pragma unroll
        for (int n = 0; n < 4; n++) { a2[n][0] = b2[0]; a2[n][1] = b2[1]; }
        #pragma unroll
        for (int j = 0; j < 16; j += 2) {
            ulonglong2 w0 = *reinterpret_cast<const ulonglong2*>(w2 + 2 * j);
            ulonglong2 w1v = *reinterpret_cast<const ulonglong2*>(w2 + 32 + 2 * j);
            #pragma unroll
            for (int n = 0; n < 4; n++) {
                ulonglong2 hx = *reinterpret_cast<const ulonglong2*>(h1u + n * H1_STR + j);
                fma2(a2[n][0], w0.x, hx.x);  fma2(a2[n][0], w0.y, hx.y);
                fma2(a2[n][1], w1v.x, hx.x); fma2(a2[n][1], w1v.y, hx.y);
            }
        }
        #pragma unroll
        for (int j = 0; j < 32; j += 2) {
            ulonglong2 w0 = *reinterpret_cast<const ulonglong2*>(w2 + W2_WHOFF + 2 * j);
            ulonglong2 w1v = *reinterpret_cast<const ulonglong2*>(w2 + W2_WHOFF + 64 + 2 * j);
            #pragma unroll
            for (int n = 0; n < 4; n++) {
                ulonglong2 hx = *reinterpret_cast<const ulonglong2*>(h2u + n * H2_STR + j);
                fma2(a2[n][0], w0.x, hx.x);  fma2(a2[n][0], w0.y, hx.y);
                fma2(a2[n][1], w1v.x, hx.x); fma2(a2[n][1], w1v.y, hx.y);
            }
        }
        #pragma unroll
        for (int n = 0; n < 4; n++) {
            float gi, gf, gg, go;
            upk(a2[n][0], gi, gf);
            upk(a2[n][1], gg, go);
            float cc = fmaf(sigf(gf), c2[n], sigf(gi) * tanh_(gg));
            c2[n] = cc;
            h2u[n * H2_STR + lane] = pk(sigf(go) * tanh_(cc));
        }
        __syncwarp();

        // ================= Layer 3 (H=16, half-warp, 2 local batches) =======
        u64 a3[2][2];
        a3[0][0] = b3[0]; a3[0][1] = b3[1];
        a3[1][0] = b3[0]; a3[1][1] = b3[1];
        #pragma unroll
        for (int j = 0; j < 32; j += 2) {
            ulonglong2 hx0 = *reinterpret_cast<const ulonglong2*>(h2self + 0 * H2_STR + j);
            ulonglong2 hx1 = *reinterpret_cast<const ulonglong2*>(h2self + 1 * H2_STR + j);
            #pragma unroll
            for (int p = 0; p < 2; p++) {
                ulonglong2 wv = *reinterpret_cast<const ulonglong2*>(w3 + p * 64 + 2 * j);
                fma2(a3[0][p], wv.x, hx0.x); fma2(a3[0][p], wv.y, hx0.y);
                fma2(a3[1][p], wv.x, hx1.x); fma2(a3[1][p], wv.y, hx1.y);
            }
        }
        #pragma unroll
        for (int j = 0; j < 16; j += 2) {
            ulonglong2 hx0 = *reinterpret_cast<const ulonglong2*>(h3self + 0 * H3_STR + j);
            ulonglong2 hx1 = *reinterpret_cast<const ulonglong2*>(h3self + 1 * H3_STR + j);
            #pragma unroll
            for (int p = 0; p < 2; p++) {
                fma2(a3[0][p], wh3r[p * 16 + j],     hx0.x);
                fma2(a3[0][p], wh3r[p * 16 + j + 1], hx0.y);
                fma2(a3[1][p], wh3r[p * 16 + j],     hx1.x);
                fma2(a3[1][p], wh3r[p * 16 + j + 1], hx1.y);
            }
        }
        #pragma unroll
        for (int ln = 0; ln < 2; ln++) {
            float gi, gf, gg, go;
            upk(a3[ln][0], gi, gf);
            upk(a3[ln][1], gg, go);
            float cc = fmaf(sigf(gf), c3[ln], sigf(gi) * tanh_(gg));
            c3[ln] = cc;
            h3u[(half * 2 + ln) * H3_STR + hl] = pk(sigf(go) * tanh_(cc));
        }
        __syncwarp();

        pc0 = pn0; pc1 = pn1;
    }

    // ---- collapsed head: lane<24 -> (batch n, class) ----
    if (lane < 24) {
        int n = lane / 6, cls = lane - n * 6;
        const float* hrow = reinterpret_cast<const float*>(h3u + n * H3_STR);
        float acc = g_bc[cls];
        #pragma unroll
        for (int u = 0; u < 16; u++)
            acc = fmaf(hrow[2 * u], g_Wc[cls * 16 + u], acc);
        out[(size_t)(b0 + n) * 6 + cls] = acc;
    }
}

// ---- precompute pre1[b][t] = Wih1 @ x[b][t] + bih1 + bhh1, lane layout ----
__global__ void __launch_bounds__(256) pre1_kernel(
    const float* __restrict__ x,
    const float* __restrict__ Wih1,
    const float* __restrict__ bih1, const float* __restrict__ bhh1)
{
    const int lane = threadIdx.x & 31;
    const int gw   = (blockIdx.x * blockDim.x + threadIdx.x) >> 5;
    const int nw   = (gridDim.x * blockDim.x) >> 5;
    const int un = lane & 15, pr = lane >> 4;
    const int rA = pr * 32 + un;       // pair0: rows (i_un, f_un); pair1: (g_un, o_un)
    const int rB = rA + 16;

    u64 wp[F];
    #pragma unroll
    for (int j = 0; j < F; j++)
        wp[j] = pkp(__ldg(Wih1 + rA * F + j), __ldg(Wih1 + rB * F + j));
    const u64 bias = pkp(bih1[rA] + bhh1[rA], bih1[rB] + bhh1[rB]);

    for (size_t bt = gw; bt < (size_t)B * T; bt += nw) {
        const float4* xp = reinterpret_cast<const float4*>(x + bt * F);
        u64 acc = bias;
        #pragma unroll
        for (int q = 0; q < F / 4; q++) {
            float4 v = __ldg(xp + q);
            fma2(acc, wp[4 * q + 0], pk(v.x));
            fma2(acc, wp[4 * q + 1], pk(v.y));
            fma2(acc, wp[4 * q + 2], pk(v.z));
            fma2(acc, wp[4 * q + 3], pk(v.w));
        }
        g_pre1[bt * 32 + un * 2 + pr] = acc;
    }
}

// Collapse the 3 linear head layers into Wc [6,16], bc [6].
__global__ void head_precompute(
    const float* __restrict__ Wfc1, const float* __restrict__ bfc1,
    const float* __restrict__ Wfc2, const float* __restrict__ bfc2,
    const float* __restrict__ Wcls, const float* __restrict__ bcls)
{
    __shared__ float tmp[6 * 128];
    const int tid = threadIdx.x;

    for (int idx = tid; idx < 6 * 128; idx += blockDim.x) {
        int j = idx / 128, p = idx % 128;
        float s = 0.0f;
        for (int q = 0; q < 32; q++)
            s += Wcls[j * 32 + q] * Wfc2[q * 128 + p];
        tmp[idx] = s;
    }
    __syncthreads();

    for (int idx = tid; idx < 6 * 16; idx += blockDim.x) {
        int j = idx / 16, u = idx % 16;
        float s = 0.0f;
        for (int p = 0; p < 128; p++)
            s += tmp[j * 128 + p] * Wfc1[p * 16 + u];
        g_Wc[idx] = s;
    }
    if (tid < 6) {
        float s = bcls[tid];
        for (int q = 0; q < 32; q++)
            s += Wcls[tid * 32 + q] * bfc2[q];
        for (int p = 0; p < 128; p++)
            s += tmp[tid * 128 + p] * bfc1[p];
        g_bc[tid] = s;
    }
}

extern "C" void kernel_launch(void* const* d_in, const int* in_sizes, int n_in,
                              void* d_out, int out_size)
{
    (void)in_sizes; (void)n_in; (void)out_size;
    const float* x    = (const float*)d_in[0];
    const float* Wih1 = (const float*)d_in[1];
    const float* Whh1 = (const float*)d_in[2];
    const float* bih1 = (const float*)d_in[3];
    const float* bhh1 = (const float*)d_in[4];
    const float* Wih2 = (const float*)d_in[5];
    const float* Whh2 = (const float*)d_in[6];
    const float* bih2 = (const float*)d_in[7];
    const float* bhh2 = (const float*)d_in[8];
    const float* Wih3 = (const float*)d_in[9];
    const float* Whh3 = (const float*)d_in[10];
    const float* bih3 = (const float*)d_in[11];
    const float* bhh3 = (const float*)d_in[12];
    const float* Wfc1 = (const float*)d_in[13];
    const float* bfc1 = (const float*)d_in[14];
    const float* Wfc2 = (const float*)d_in[15];
    const float* bfc2 = (const float*)d_in[16];
    const float* Wcls = (const float*)d_in[17];
    const float* bcls = (const float*)d_in[18];
    float* out = (float*)d_out;

    static bool attr_set = false;
    if (!attr_set) {
        cudaFuncSetAttribute(lstm_fused,
                             cudaFuncAttributeMaxDynamicSharedMemorySize,
                             SMEM_BYTES);
        attr_set = true;
    }

    pre1_kernel<<<2048, 256>>>(x, Wih1, bih1, bhh1);
    head_precompute<<<1, 256>>>(Wfc1, bfc1, Wfc2, bfc2, Wcls, bcls);
    lstm_fused<<<GRID, THREADS, SMEM_BYTES>>>(
        Whh1, Wih2, Whh2, bih2, bhh2,
        Wih3, Whh3, bih3, bhh3, out);
}